// round 13
// baseline (speedup 1.0000x reference)
#include <cuda_runtime.h>
#include <cuda_bf16.h>

#define BATCH  32
#define SEQ    128
#define NSTEP  127
#define DK     128
#define NSKILL 256

#define CL   4      // cluster size (CTAs per batch)
#define SKP  64     // skills per CTA
#define NT   384    // 8 MMA/state warps + 4 chain warps
#define WST  132    // padded small-weight row stride (floats)
#define AST  136    // bf16 tile row stride (elements) -> 272B, conflict-free ldmatrix

// ------------------------- device scratch -------------------------
__device__ float g_le[BATCH * SEQ * DK];
__device__ float g_Al[BATCH * NSTEP * DK];
__device__ float g_Ag[BATCH * NSTEP * DK];
__device__ float g_Af[BATCH * NSTEP * DK];
__device__ float g_Ap[BATCH * NSTEP * DK];

__device__ __forceinline__ float sigm(float x) { return 1.f / (1.f + __expf(-x)); }

// ---------- cluster / mbarrier helpers ----------
__device__ __forceinline__ unsigned smem_u32(const void* p) {
    unsigned a;
    asm("{ .reg .u64 t; cvta.to.shared.u64 t, %1; cvt.u32.u64 %0, t; }" : "=r"(a) : "l"(p));
    return a;
}
__device__ __forceinline__ unsigned mapa_rank(unsigned a, int rank) {
    unsigned d;
    asm("mapa.shared::cluster.u32 %0, %1, %2;" : "=r"(d) : "r"(a), "r"(rank));
    return d;
}
__device__ __forceinline__ void st_cluster_f32(unsigned a, float v) {
    asm volatile("st.shared::cluster.f32 [%0], %1;" :: "r"(a), "f"(v) : "memory");
}
__device__ __forceinline__ void mbar_init(unsigned a, unsigned cnt) {
    asm volatile("mbarrier.init.shared.b64 [%0], %1;" :: "r"(a), "r"(cnt) : "memory");
}
__device__ __forceinline__ void arrive_cluster(unsigned a) {
    asm volatile("mbarrier.arrive.release.cluster.shared::cluster.b64 _, [%0];"
                 :: "r"(a) : "memory");
}
__device__ __forceinline__ void wait_parity(unsigned a, unsigned ph) {
    unsigned done;
    asm volatile(
        "{\n\t.reg .pred p;\n\t"
        "mbarrier.try_wait.parity.acquire.cluster.shared::cta.b64 p, [%1], %2;\n\t"
        "selp.b32 %0, 1, 0, p;\n\t}"
        : "=r"(done) : "r"(a), "r"(ph) : "memory");
    if (!done) {
        asm volatile(
            "{\n\t.reg .pred P1;\n\t"
            "W_%=:\n\t"
            "mbarrier.try_wait.parity.acquire.cluster.shared::cta.b64 P1, [%0], %1, 0x989680;\n\t"
            "@P1 bra.uni D_%=;\n\t"
            "bra.uni W_%=;\n\t"
            "D_%=:\n\t}"
            :: "r"(a), "r"(ph) : "memory");
    }
}
__device__ __forceinline__ void cluster_sync_all() {
    asm volatile("barrier.cluster.arrive.aligned;" ::: "memory");
    asm volatile("barrier.cluster.wait.aligned;" ::: "memory");
}
__device__ __forceinline__ unsigned my_cluster_rank() {
    unsigned r;
    asm("mov.u32 %0, %%cluster_ctarank;" : "=r"(r));
    return r;
}
__device__ __forceinline__ void bar_sync(int id, int n) {
    asm volatile("bar.sync %0, %1;" :: "r"(id), "r"(n) : "memory");
}

// ---------- mma.sync / ldmatrix (compute_80 features, legal on sm_103) ----------
#define LDSM4(r, addr) \
    asm volatile("ldmatrix.sync.aligned.m8n8.x4.shared.b16 {%0,%1,%2,%3}, [%4];" \
        : "=r"((r)[0]), "=r"((r)[1]), "=r"((r)[2]), "=r"((r)[3]) : "r"(addr))

#define MMA16816(d, a, b0, b1) \
    asm volatile("mma.sync.aligned.m16n8k16.row.col.f32.bf16.bf16.f32 " \
        "{%0,%1,%2,%3}, {%4,%5,%6,%7}, {%8,%9}, {%0,%1,%2,%3};" \
        : "+f"((d)[0]), "+f"((d)[1]), "+f"((d)[2]), "+f"((d)[3]) \
        : "r"((a)[0]), "r"((a)[1]), "r"((a)[2]), "r"((a)[3]), "r"(b0), "r"(b1))

// split fp32 -> bf16 hi + bf16 lo store (tile row stride AST elements)
__device__ __forceinline__ void st_split(char* smc, unsigned hi_base, int s, int c, float v) {
    __nv_bfloat16 hi = __float2bfloat16(v);
    float hif = __uint_as_float(((unsigned)__bfloat16_as_ushort(hi)) << 16);
    __nv_bfloat16 lo = __float2bfloat16(v - hif);
    unsigned off = hi_base + (unsigned)(s * AST + c) * 2;
    *(__nv_bfloat16*)(smc + off) = hi;
    *(__nv_bfloat16*)(smc + off + 17408) = lo;   // lo tile = hi tile + 64*272
}

// ------------------------------------------------------------------
// Kernel 1: le[b,s,:] = [ex | at | ans] @ W1^T + b1   (unchanged)
// ------------------------------------------------------------------
__global__ void le_kernel(const int* __restrict__ eid, const int* __restrict__ atid,
                          const int* __restrict__ ansv,
                          const float* __restrict__ ex_table, const float* __restrict__ at_table,
                          const float* __restrict__ W1, const float* __restrict__ b1)
{
    __shared__ float X[8][256];
    __shared__ float AV[8];
    const int tid  = threadIdx.x;
    const int base = blockIdx.x * 8;

    for (int idx = tid; idx < 8 * 256; idx += 128) {
        int r = idx >> 8, c = idx & 255;
        int p = base + r;
        float v;
        if (c < 128) v = ex_table[eid[p] * DK + c];
        else         v = at_table[atid[p] * DK + (c - 128)];
        X[r][c] = v;
    }
    if (tid < 8) AV[tid] = (float)ansv[base + tid];
    __syncthreads();

    const int k = tid;
    const float4* wrow = (const float4*)(W1 + k * 384);

    float rs = 0.f;
#pragma unroll
    for (int j4 = 64; j4 < 96; ++j4) { float4 w = wrow[j4]; rs += w.x + w.y + w.z + w.w; }

    float acc[8];
    const float bk = b1[k];
#pragma unroll
    for (int r = 0; r < 8; ++r) acc[r] = bk + AV[r] * rs;

    for (int j4 = 0; j4 < 64; ++j4) {
        float4 w = wrow[j4];
#pragma unroll
        for (int r = 0; r < 8; ++r) {
            float4 x = ((const float4*)X[r])[j4];
            acc[r] = fmaf(x.x, w.x, acc[r]);
            acc[r] = fmaf(x.y, w.y, acc[r]);
            acc[r] = fmaf(x.z, w.z, acc[r]);
            acc[r] = fmaf(x.w, w.w, acc[r]);
        }
    }
#pragma unroll
    for (int r = 0; r < 8; ++r) g_le[(base + r) * DK + k] = acc[r];
}

// ------------------------------------------------------------------
// Kernel 2: hoisted per-step constants. (unchanged)
// ------------------------------------------------------------------
__global__ void pre_kernel(const int* __restrict__ eid, const int* __restrict__ itid,
                           const float* __restrict__ ex_table, const float* __restrict__ it_table,
                           const float* __restrict__ Wl, const float* __restrict__ bl,
                           const float* __restrict__ Wg, const float* __restrict__ bg,
                           const float* __restrict__ Wf, const float* __restrict__ bf,
                           const float* __restrict__ Wp, const float* __restrict__ bp)
{
    __shared__ float X[16][512];
    const int tid  = threadIdx.x;
    const int base = blockIdx.x * 16;

    for (int idx = tid; idx < 16 * 512; idx += 512) {
        int r = idx >> 9, c = idx & 511;
        int p = base + r;
        int b = p / NSTEP, t = p % NSTEP;
        float v;
        if (c < 128)      v = (t == 0) ? 0.f : g_le[(b * SEQ + t - 1) * DK + c];
        else if (c < 256) v = it_table[itid[b * SEQ + t + 1] * DK + (c - 128)];
        else if (c < 384) v = g_le[(b * SEQ + t) * DK + (c - 256)];
        else              v = ex_table[eid[b * SEQ + t + 1] * DK + (c - 384)];
        X[r][c] = v;
    }
    __syncthreads();

    const int g = tid >> 7, k = tid & 127;
    float acc[16];

    if (g <= 1) {
        const float* W = (g == 0) ? Wl : Wg;
        const float  bk = (g == 0) ? bl[k] : bg[k];
#pragma unroll
        for (int r = 0; r < 16; ++r) acc[r] = bk;
        const float4* wrow = (const float4*)(W + k * 512);
        for (int j4 = 0; j4 < 96; ++j4) {
            float4 w = wrow[j4];
#pragma unroll
            for (int r = 0; r < 16; ++r) {
                float4 x = ((const float4*)X[r])[j4];
                acc[r] = fmaf(x.x, w.x, acc[r]);
                acc[r] = fmaf(x.y, w.y, acc[r]);
                acc[r] = fmaf(x.z, w.z, acc[r]);
                acc[r] = fmaf(x.w, w.w, acc[r]);
            }
        }
        float* dst = (g == 0) ? g_Al : g_Ag;
#pragma unroll
        for (int r = 0; r < 16; ++r) dst[(base + r) * DK + k] = acc[r];
    } else if (g == 2) {
        const float bk = bf[k];
#pragma unroll
        for (int r = 0; r < 16; ++r) acc[r] = bk;
        const float4* wrow = (const float4*)(Wf + k * 384 + 256);
        for (int j4 = 0; j4 < 32; ++j4) {
            float4 w = wrow[j4];
#pragma unroll
            for (int r = 0; r < 16; ++r) {
                float4 x = ((const float4*)(X[r] + 128))[j4];
                acc[r] = fmaf(x.x, w.x, acc[r]);
                acc[r] = fmaf(x.y, w.y, acc[r]);
                acc[r] = fmaf(x.z, w.z, acc[r]);
                acc[r] = fmaf(x.w, w.w, acc[r]);
            }
        }
#pragma unroll
        for (int r = 0; r < 16; ++r) g_Af[(base + r) * DK + k] = acc[r];
    } else {
        const float bk = bp[k];
#pragma unroll
        for (int r = 0; r < 16; ++r) acc[r] = bk;
        const float4* wrow = (const float4*)(Wp + k * 256);
        for (int j4 = 0; j4 < 32; ++j4) {
            float4 w = wrow[j4];
#pragma unroll
            for (int r = 0; r < 16; ++r) {
                float4 x = ((const float4*)(X[r] + 384))[j4];
                acc[r] = fmaf(x.x, w.x, acc[r]);
                acc[r] = fmaf(x.y, w.y, acc[r]);
                acc[r] = fmaf(x.z, w.z, acc[r]);
                acc[r] = fmaf(x.w, w.w, acc[r]);
            }
        }
#pragma unroll
        for (int r = 0; r < 16; ++r) g_Ap[(base + r) * DK + k] = acc[r];
    }
}

// ------------------------------------------------------------------
// Kernel 3: mma.sync recurrent loop.
//   D[c][s] = sum_j Wf0[c][j] h[s][j]; A=Wf0 (static hi/lo), B=h (hi/lo, 2 bufs).
//   h fp32 kept in registers in D-fragment layout.
// SMEM byte offsets:
static constexpr int OFF_AHI  = 0;                        // 128*272 = 34816
static constexpr int OFF_ALO  = 34816;                    // 34816
static constexpr int OFF_BT   = 69632;                    // 4 tiles * 17408 (buf0hi,buf0lo,buf1hi,buf1lo)
static constexpr int OFF_WL2  = 139264;                   // 32*132*4 = 16896
static constexpr int OFF_WG2  = 156160;
static constexpr int OFF_WF1  = 173056;
static constexpr int OFF_WP1  = 189952;
static constexpr int OFF_MAIL = 206848;                   // 2*4*128*4 = 4096
static constexpr int OFF_LGF  = 210944;                   // 2*128*4
static constexpr int OFF_CFF  = 211968;
static constexpr int OFF_HT   = 212992;                   // 128*4
static constexpr int OFF_LGT  = 213504;                   // 64*4
static constexpr int OFF_KV   = 213760;                   // 2*64*4
static constexpr int OFF_BAR  = 214272;                   // 6 u64
static constexpr int SMEM_BYTES = 214336;                 // ~209.3 KB

#define BARH_B(buf)  (OFF_BAR + (buf) * 8)
#define BARLG_B(buf) (OFF_BAR + 16 + (buf) * 8)
#define BARCF_B(buf) (OFF_BAR + 32 + (buf) * 8)

__global__ void __cluster_dims__(CL, 1, 1) __launch_bounds__(NT, 1)
recur_kernel(const int* __restrict__ eid, const float* __restrict__ qmat,
             const float* __restrict__ Wl, const float* __restrict__ Wg,
             const float* __restrict__ Wf, const float* __restrict__ Wp,
             const float* __restrict__ h0, float* __restrict__ out)
{
    extern __shared__ float sm[];
    char*  smc  = (char*)sm;
    float* wl2  = (float*)(smc + OFF_WL2);
    float* wg2  = (float*)(smc + OFF_WG2);
    float* wf1  = (float*)(smc + OFF_WF1);
    float* wp1  = (float*)(smc + OFF_WP1);
    float* mail = (float*)(smc + OFF_MAIL);
    float* LGf  = (float*)(smc + OFF_LGF);
    float* cff  = (float*)(smc + OFF_CFF);
    float* htil = (float*)(smc + OFF_HT);
    float* lgt  = (float*)(smc + OFF_LGT);
    float* kv   = (float*)(smc + OFF_KV);

    const unsigned sbase = smem_u32(sm);
    const int tid   = threadIdx.x;
    const int wid   = tid >> 5;
    const int lane  = tid & 31;
    const int b     = blockIdx.x / CL;
    const int r     = (int)my_cluster_rank();
    const int sBase = r * SKP;

    if (tid == 0) {
        mbar_init(sbase + BARH_B(0), 256);  mbar_init(sbase + BARH_B(1), 256);
        mbar_init(sbase + BARLG_B(0), 128); mbar_init(sbase + BARLG_B(1), 128);
        mbar_init(sbase + BARCF_B(0), 128); mbar_init(sbase + BARCF_B(1), 128);
    }

    // ---- prologue: Wf0 split into A hi/lo tiles ----
    for (int idx = tid; idx < DK * DK; idx += NT) {
        int c = idx >> 7, k = idx & 127;
        float w = Wf[c * 384 + k];
        __nv_bfloat16 hi = __float2bfloat16(w);
        float hif = __uint_as_float(((unsigned)__bfloat16_as_ushort(hi)) << 16);
        __nv_bfloat16 lo = __float2bfloat16(w - hif);
        unsigned off = (unsigned)(c * AST + k) * 2;
        *(__nv_bfloat16*)(smc + OFF_AHI + off) = hi;
        *(__nv_bfloat16*)(smc + OFF_ALO + off) = lo;
    }
    for (int idx = tid; idx < 32 * DK; idx += NT) {
        int row = idx >> 7, k = idx & 127;
        int gk = r * 32 + row;
        wl2[row * WST + k] = Wl[gk * 512 + 384 + k];
        wg2[row * WST + k] = Wg[gk * 512 + 384 + k];
        wf1[row * WST + k] = Wf[gk * 384 + 128 + k];
        wp1[row * WST + k] = Wp[gk * 256 + 128 + k];
    }
    if (tid < SKP) kv[tid] = qmat[eid[b * SEQ] * NSKILL + sBase + tid];
    __syncthreads();

    // MMA-thread identity
    const int grp  = lane >> 2, tid4 = lane & 3;
    const int c0   = wid * 16 + grp;          // wid<8 only; c1 = c0+8
    // ldmatrix address components
    const unsigned aoff = (unsigned)((wid * 16 + (lane & 15)) * AST + ((lane >> 4) << 3)) * 2;
    const int brow = (lane & 7) + ((lane >> 4) << 3);
    const int bcol = ((lane >> 3) & 1) << 3;

    float h[8][4];   // h[nt][q]: q0=(c0,s0), q1=(c0,s0+1), q2=(c1,s0), q3=(c1,s0+1)

    if (tid < 256) {
        // load h0 into regs + fill Bt[0] tiles + initial pk
        float pk0 = 0.f, pk1 = 0.f;
#pragma unroll
        for (int nt = 0; nt < 8; ++nt) {
            const int s0 = nt * 8 + tid4 * 2;
            const float k0 = kv[s0], k1 = kv[s0 + 1];
            h[nt][0] = h0[(sBase + s0) * DK + c0];
            h[nt][1] = h0[(sBase + s0 + 1) * DK + c0];
            h[nt][2] = h0[(sBase + s0) * DK + c0 + 8];
            h[nt][3] = h0[(sBase + s0 + 1) * DK + c0 + 8];
            st_split(smc, OFF_BT, s0,     c0,     h[nt][0]);
            st_split(smc, OFF_BT, s0 + 1, c0,     h[nt][1]);
            st_split(smc, OFF_BT, s0,     c0 + 8, h[nt][2]);
            st_split(smc, OFF_BT, s0 + 1, c0 + 8, h[nt][3]);
            pk0 = fmaf(k0, h[nt][0], pk0); pk0 = fmaf(k1, h[nt][1], pk0);
            pk1 = fmaf(k0, h[nt][2], pk1); pk1 = fmaf(k1, h[nt][3], pk1);
        }
        pk0 += __shfl_xor_sync(0xffffffffu, pk0, 1);
        pk0 += __shfl_xor_sync(0xffffffffu, pk0, 2);
        pk1 += __shfl_xor_sync(0xffffffffu, pk1, 1);
        pk1 += __shfl_xor_sync(0xffffffffu, pk1, 2);
        if (tid4 == 0) {
            unsigned la = sbase + OFF_MAIL + (unsigned)(r * DK + c0) * 4;
#pragma unroll
            for (int rr = 0; rr < CL; ++rr) {
                unsigned ra = mapa_rank(la, rr);
                st_cluster_f32(ra, pk0);
                st_cluster_f32(ra + 32, pk1);   // c0+8 -> +8 floats
            }
        }
    }
    __syncthreads();
    cluster_sync_all();   // barriers, tiles, initial mail visible cluster-wide

    if (tid < 256) {
        // ================= MMA / state warps =================
        int phLG[2] = {0, 0}, phCF[2] = {0, 0};

        for (int t = 0; t < NSTEP; ++t) {
            const int buf = t & 1, nbuf = buf ^ 1;

            // ---- GEMM: D = Ahi*Bhi + Ahi*Blo + Alo*Bhi ----
            float acc[8][4];
#pragma unroll
            for (int nt = 0; nt < 8; ++nt)
#pragma unroll
                for (int q = 0; q < 4; ++q) acc[nt][q] = 0.f;

            const unsigned bb = sbase + OFF_BT + (unsigned)buf * 34816u;
#pragma unroll
            for (int kk = 0; kk < 8; ++kk) {
                unsigned ah[4], al[4];
                LDSM4(ah, sbase + OFF_AHI + aoff + kk * 32);
                LDSM4(al, sbase + OFF_ALO + aoff + kk * 32);
#pragma unroll
                for (int ntp = 0; ntp < 4; ++ntp) {
                    unsigned bh[4], bl[4];
                    unsigned bo = (unsigned)((ntp * 16 + brow) * AST + bcol + kk * 16) * 2;
                    LDSM4(bh, bb + bo);
                    LDSM4(bl, bb + 17408 + bo);
                    MMA16816(acc[2 * ntp],     ah, bh[0], bh[1]);
                    MMA16816(acc[2 * ntp],     ah, bl[0], bl[1]);
                    MMA16816(acc[2 * ntp],     al, bh[0], bh[1]);
                    MMA16816(acc[2 * ntp + 1], ah, bh[2], bh[3]);
                    MMA16816(acc[2 * ntp + 1], ah, bl[2], bl[3]);
                    MMA16816(acc[2 * ntp + 1], al, bh[2], bh[3]);
                }
            }

            // ---- wait LG + cf (chain produced them under the GEMM shadow) ----
            wait_parity(sbase + BARLG_B(buf), (unsigned)phLG[buf]); phLG[buf] ^= 1;
            wait_parity(sbase + BARCF_B(buf), (unsigned)phCF[buf]); phCF[buf] ^= 1;

            // ---- E: f, h update, re-split store, pk ----
            const float lg0 = LGf[buf * DK + c0], lg1 = LGf[buf * DK + c0 + 8];
            const float cf0 = cff[buf * DK + c0], cf1 = cff[buf * DK + c0 + 8];
            const unsigned nb = OFF_BT + (unsigned)nbuf * 34816u;
            float pk0 = 0.f, pk1 = 0.f;
#pragma unroll
            for (int nt = 0; nt < 8; ++nt) {
                const int s0 = nt * 8 + tid4 * 2;
                const float2 kc = *(const float2*)(kv + buf * SKP + s0);
                const float2 kn = *(const float2*)(kv + nbuf * SKP + s0);
                float n0 = fmaf(sigm(acc[nt][0] + cf0), h[nt][0], kc.x * lg0);
                float n1 = fmaf(sigm(acc[nt][1] + cf0), h[nt][1], kc.y * lg0);
                float n2 = fmaf(sigm(acc[nt][2] + cf1), h[nt][2], kc.x * lg1);
                float n3 = fmaf(sigm(acc[nt][3] + cf1), h[nt][3], kc.y * lg1);
                h[nt][0] = n0; h[nt][1] = n1; h[nt][2] = n2; h[nt][3] = n3;
                st_split(smc, nb, s0,     c0,     n0);
                st_split(smc, nb, s0 + 1, c0,     n1);
                st_split(smc, nb, s0,     c0 + 8, n2);
                st_split(smc, nb, s0 + 1, c0 + 8, n3);
                pk0 = fmaf(kn.x, n0, pk0); pk0 = fmaf(kn.y, n1, pk0);
                pk1 = fmaf(kn.x, n2, pk1); pk1 = fmaf(kn.y, n3, pk1);
            }
            pk0 += __shfl_xor_sync(0xffffffffu, pk0, 1);
            pk0 += __shfl_xor_sync(0xffffffffu, pk0, 2);
            pk1 += __shfl_xor_sync(0xffffffffu, pk1, 1);
            pk1 += __shfl_xor_sync(0xffffffffu, pk1, 2);
            if (tid4 == 0) {
                unsigned la = sbase + OFF_MAIL + (unsigned)((nbuf * CL + r) * DK + c0) * 4;
#pragma unroll
                for (int rr = 0; rr < CL; ++rr) {
                    unsigned ra = mapa_rank(la, rr);
                    st_cluster_f32(ra, pk0);
                    st_cluster_f32(ra + 32, pk1);
                }
#pragma unroll
                for (int rr = 0; rr < CL; ++rr)
                    arrive_cluster(mapa_rank(sbase + BARH_B(nbuf), rr));
            }
            bar_sync(1, 256);   // Bt[nbuf] complete before next step's ldmatrix
        }
    } else {
        // ================= chain warps (128 threads) =================
        const int tc   = tid - 256;
        const int rowB = tc >> 1, qB = tc & 1;
        const int rowD = tc >> 2, qD = tc & 3;
        const float* wB = ((rowB < 32) ? (wl2 + rowB * WST) : (wg2 + (rowB - 32) * WST)) + qB * 64;
        int phH[2] = {0, 0}, phLG[2] = {0, 0};

        for (int t = 0; t < NSTEP; ++t) {
            const int buf = t & 1, nbuf = buf ^ 1;
            const int ptA = (b * NSTEP + t) * DK;

            if (t > 0) { wait_parity(sbase + BARH_B(buf), (unsigned)phH[buf]); phH[buf] ^= 1; }
            {
                const float* m = mail + buf * CL * DK + tc;
                htil[tc] = m[0] + m[DK] + m[2 * DK] + m[3 * DK];
            }
            bar_sync(2, 128);

            if (qD == 0) {
                const int e = eid[b * SEQ + t + 1] * NSKILL + sBase;
                kv[nbuf * SKP + rowD]      = qmat[e + rowD];
                kv[nbuf * SKP + 32 + rowD] = qmat[e + 32 + rowD];
            }

            // lg/gate partial dots
            {
                float a = 0.f;
                const float* hp = htil + qB * 64;
#pragma unroll
                for (int j4 = 0; j4 < 16; ++j4) {
                    float4 w = ((const float4*)wB)[j4];
                    float4 hh = ((const float4*)hp)[j4];
                    a = fmaf(hh.x, w.x, a); a = fmaf(hh.y, w.y, a);
                    a = fmaf(hh.z, w.z, a); a = fmaf(hh.w, w.w, a);
                }
                a += __shfl_xor_sync(0xffffffffu, a, 1);
                if (qB == 0) lgt[rowB] = a;
            }
            bar_sync(2, 128);

            // LG -> all ranks
            if (tc < 32) {
                const int k = r * 32 + tc;
                float lgp = g_Al[ptA + k] + lgt[tc];
                float gtp = g_Ag[ptA + k] + lgt[32 + tc];
                float val = sigm(gtp) * sigm(2.f * lgp);
                unsigned la = sbase + OFF_LGF + (unsigned)(buf * DK + k) * 4;
#pragma unroll
                for (int rr = 0; rr < CL; ++rr) st_cluster_f32(mapa_rank(la, rr), val);
#pragma unroll
                for (int rr = 0; rr < CL; ++rr)
                    arrive_cluster(mapa_rank(sbase + BARLG_B(buf), rr));
            }

            // prediction for step t-1
            if (t > 0) {
                float a = 0.f;
                const float* wf = wp1 + rowD * WST + qD * 32;
                const float* hp = htil + qD * 32;
#pragma unroll
                for (int j4 = 0; j4 < 8; ++j4) {
                    float4 w = ((const float4*)wf)[j4];
                    float4 hh = ((const float4*)hp)[j4];
                    a = fmaf(hh.x, w.x, a); a = fmaf(hh.y, w.y, a);
                    a = fmaf(hh.z, w.z, a); a = fmaf(hh.w, w.w, a);
                }
                a += __shfl_xor_sync(0xffffffffu, a, 1);
                a += __shfl_xor_sync(0xffffffffu, a, 2);
                if (qD == 0) {
                    const int k = r * 32 + rowD;
                    out[(b * NSTEP + (t - 1)) * DK + k] =
                        sigm(a + g_Ap[(b * NSTEP + (t - 1)) * DK + k]);
                }
            }

            // cf -> all ranks
            wait_parity(sbase + BARLG_B(buf), (unsigned)phLG[buf]); phLG[buf] ^= 1;
            {
                float a = 0.f;
                const float* wf = wf1 + rowD * WST + qD * 32;
                const float* lp = LGf + buf * DK + qD * 32;
#pragma unroll
                for (int j4 = 0; j4 < 8; ++j4) {
                    float4 w = ((const float4*)wf)[j4];
                    float4 hh = ((const float4*)lp)[j4];
                    a = fmaf(hh.x, w.x, a); a = fmaf(hh.y, w.y, a);
                    a = fmaf(hh.z, w.z, a); a = fmaf(hh.w, w.w, a);
                }
                a += __shfl_xor_sync(0xffffffffu, a, 1);
                a += __shfl_xor_sync(0xffffffffu, a, 2);
                if (qD == 0) {
                    const int k = r * 32 + rowD;
                    float val = a + g_Af[ptA + k];
                    unsigned la = sbase + OFF_CFF + (unsigned)(buf * DK + k) * 4;
#pragma unroll
                    for (int rr = 0; rr < CL; ++rr) st_cluster_f32(mapa_rank(la, rr), val);
#pragma unroll
                    for (int rr = 0; rr < CL; ++rr)
                        arrive_cluster(mapa_rank(sbase + BARCF_B(buf), rr));
                }
            }
        }

        // epilogue: final exchange + last prediction
        wait_parity(sbase + BARH_B(NSTEP & 1), (unsigned)phH[NSTEP & 1]);
        {
            const float* m = mail + (NSTEP & 1) * CL * DK + tc;
            htil[tc] = m[0] + m[DK] + m[2 * DK] + m[3 * DK];
        }
        bar_sync(2, 128);
        {
            float a = 0.f;
            const float* wf = wp1 + rowD * WST + qD * 32;
            const float* hp = htil + qD * 32;
#pragma unroll
            for (int j4 = 0; j4 < 8; ++j4) {
                float4 w = ((const float4*)wf)[j4];
                float4 hh = ((const float4*)hp)[j4];
                a = fmaf(hh.x, w.x, a); a = fmaf(hh.y, w.y, a);
                a = fmaf(hh.z, w.z, a); a = fmaf(hh.w, w.w, a);
            }
            a += __shfl_xor_sync(0xffffffffu, a, 1);
            a += __shfl_xor_sync(0xffffffffu, a, 2);
            if (qD == 0) {
                const int k = r * 32 + rowD;
                out[(b * NSTEP + (NSTEP - 1)) * DK + k] =
                    sigm(a + g_Ap[(b * NSTEP + (NSTEP - 1)) * DK + k]);
            }
        }
    }

    cluster_sync_all();   // exit safety for in-flight DSMEM traffic
}

// ------------------------------------------------------------------
extern "C" void kernel_launch(void* const* d_in, const int* in_sizes, int n_in,
                              void* d_out, int out_size)
{
    const int*   eid      = (const int*)d_in[0];
    const int*   atid     = (const int*)d_in[1];
    const int*   itid     = (const int*)d_in[2];
    const int*   ansv     = (const int*)d_in[3];
    const float* qmat     = (const float*)d_in[4];
    const float* ex_table = (const float*)d_in[5];
    const float* at_table = (const float*)d_in[6];
    const float* it_table = (const float*)d_in[7];
    const float* W1       = (const float*)d_in[8];
    const float* b1       = (const float*)d_in[9];
    const float* Wl       = (const float*)d_in[10];
    const float* bl       = (const float*)d_in[11];
    const float* Wg       = (const float*)d_in[12];
    const float* bg       = (const float*)d_in[13];
    const float* Wf       = (const float*)d_in[14];
    const float* bf       = (const float*)d_in[15];
    const float* Wp       = (const float*)d_in[16];
    const float* bp       = (const float*)d_in[17];
    const float* h0       = (const float*)d_in[18];
    float* out = (float*)d_out;

    cudaFuncSetAttribute(recur_kernel, cudaFuncAttributeMaxDynamicSharedMemorySize, SMEM_BYTES);

    le_kernel<<<(BATCH * SEQ) / 8, 128>>>(eid, atid, ansv, ex_table, at_table, W1, b1);
    pre_kernel<<<(BATCH * NSTEP) / 16, 512>>>(eid, itid, ex_table, it_table,
                                              Wl, bl, Wg, bg, Wf, bf, Wp, bp);
    recur_kernel<<<BATCH * CL, NT, SMEM_BYTES>>>(eid, qmat, Wl, Wg, Wf, Wp, h0, out);
}

// round 15
// speedup vs baseline: 1.1114x; 1.1114x over previous
#include <cuda_runtime.h>
#include <cuda_bf16.h>

#define BATCH  32
#define SEQ    128
#define NSTEP  127
#define DK     128
#define NSKILL 256
#define CL   4
#define SKP  64
#define NT   384
#define WST  132
#define AST  136
#define HST  132

__device__ float g_le[BATCH * SEQ * DK];
__device__ float g_Al[BATCH * NSTEP * DK];
__device__ float g_Ag[BATCH * NSTEP * DK];
__device__ float g_Af[BATCH * NSTEP * DK];
__device__ float g_Ap[BATCH * NSTEP * DK];

__device__ __forceinline__ float sigm(float x) { return 1.f / (1.f + __expf(-x)); }
__device__ __forceinline__ float sigt(float x) {
    float t; asm("tanh.approx.f32 %0, %1;" : "=f"(t) : "f"(x * 0.5f));
    return fmaf(t, 0.5f, 0.5f);
}
__device__ __forceinline__ unsigned long long fma2(unsigned long long a,
                                                   unsigned long long b,
                                                   unsigned long long c) {
    unsigned long long d;
    asm("fma.rn.f32x2 %0, %1, %2, %3;" : "=l"(d) : "l"(a), "l"(b), "l"(c));
    return d;
}
__device__ __forceinline__ unsigned long long f2dup(float x) {
    unsigned long long u; asm("mov.b64 %0, {%1, %1};" : "=l"(u) : "f"(x)); return u;
}
__device__ __forceinline__ float2 f2unpack(unsigned long long u) {
    float2 r; asm("mov.b64 {%0, %1}, %2;" : "=f"(r.x), "=f"(r.y) : "l"(u)); return r;
}
__device__ __forceinline__ unsigned bfpack(float lo, float hi) {
    unsigned d;
    asm("cvt.rn.satfinite.bf16x2.f32 %0, %1, %2;" : "=r"(d) : "f"(hi), "f"(lo));
    return d;
}
__device__ __forceinline__ unsigned smem_u32(const void* p) {
    unsigned a;
    asm("{ .reg .u64 t; cvta.to.shared.u64 t, %1; cvt.u32.u64 %0, t; }" : "=r"(a) : "l"(p));
    return a;
}
__device__ __forceinline__ unsigned mapa_rank(unsigned a, int rank) {
    unsigned d;
    asm("mapa.shared::cluster.u32 %0, %1, %2;" : "=r"(d) : "r"(a), "r"(rank));
    return d;
}
__device__ __forceinline__ void st_cluster_f32(unsigned a, float v) {
    asm volatile("st.shared::cluster.f32 [%0], %1;" :: "r"(a), "f"(v) : "memory");
}
__device__ __forceinline__ void mbar_init(unsigned a, unsigned cnt) {
    asm volatile("mbarrier.init.shared.b64 [%0], %1;" :: "r"(a), "r"(cnt) : "memory");
}
__device__ __forceinline__ void arrive_cluster(unsigned a) {
    asm volatile("mbarrier.arrive.release.cluster.shared::cluster.b64 _, [%0];"
                 :: "r"(a) : "memory");
}
__device__ __forceinline__ void wait_parity(unsigned a, unsigned ph) {
    unsigned done;
    asm volatile(
        "{\n\t.reg .pred p;\n\t"
        "mbarrier.try_wait.parity.acquire.cluster.shared::cta.b64 p, [%1], %2;\n\t"
        "selp.b32 %0, 1, 0, p;\n\t}"
        : "=r"(done) : "r"(a), "r"(ph) : "memory");
    if (!done) {
        asm volatile(
            "{\n\t.reg .pred P1;\n\t"
            "W_%=:\n\t"
            "mbarrier.try_wait.parity.acquire.cluster.shared::cta.b64 P1, [%0], %1, 0x989680;\n\t"
            "@P1 bra.uni D_%=;\n\t"
            "bra.uni W_%=;\n\t"
            "D_%=:\n\t}"
            :: "r"(a), "r"(ph) : "memory");
    }
}
__device__ __forceinline__ void cluster_sync_all() {
    asm volatile("barrier.cluster.arrive.aligned;" ::: "memory");
    asm volatile("barrier.cluster.wait.aligned;" ::: "memory");
}
__device__ __forceinline__ unsigned my_cluster_rank() {
    unsigned r; asm("mov.u32 %0, %%cluster_ctarank;" : "=r"(r)); return r;
}
__device__ __forceinline__ void bar_sync(int id, int n) {
    asm volatile("bar.sync %0, %1;" :: "r"(id), "r"(n) : "memory");
}

#define LDSM4(r, addr) \
    asm volatile("ldmatrix.sync.aligned.m8n8.x4.shared.b16 {%0,%1,%2,%3}, [%4];" \
        : "=r"((r)[0]), "=r"((r)[1]), "=r"((r)[2]), "=r"((r)[3]) : "r"(addr))
#define MMA16816(d, a, b0, b1) \
    asm volatile("mma.sync.aligned.m16n8k16.row.col.f32.bf16.bf16.f32 " \
        "{%0,%1,%2,%3}, {%4,%5,%6,%7}, {%8,%9}, {%0,%1,%2,%3};" \
        : "+f"((d)[0]), "+f"((d)[1]), "+f"((d)[2]), "+f"((d)[3]) \
        : "r"((a)[0]), "r"((a)[1]), "r"((a)[2]), "r"((a)[3]), "r"(b0), "r"(b1))

__device__ __forceinline__ void st_split(char* smc, unsigned hi_base, int s, int c, float v) {
    __nv_bfloat16 hi = __float2bfloat16(v);
    float hif = __uint_as_float(((unsigned)__bfloat16_as_ushort(hi)) << 16);
    __nv_bfloat16 lo = __float2bfloat16(v - hif);
    unsigned off = hi_base + (unsigned)(s * AST + c) * 2;
    *(__nv_bfloat16*)(smc + off) = hi;
    *(__nv_bfloat16*)(smc + off + 17408) = lo;
}

// ------------------------------------------------------------------
__global__ void le_kernel(const int* __restrict__ eid, const int* __restrict__ atid,
                          const int* __restrict__ ansv,
                          const float* __restrict__ ex_table, const float* __restrict__ at_table,
                          const float* __restrict__ W1, const float* __restrict__ b1)
{
    __shared__ float X[8][256];
    __shared__ float AV[8];
    const int tid  = threadIdx.x;
    const int base = blockIdx.x * 8;

    for (int idx = tid; idx < 8 * 256; idx += 128) {
        int r = idx >> 8, c = idx & 255;
        int p = base + r;
        float v;
        if (c < 128) v = ex_table[eid[p] * DK + c];
        else         v = at_table[atid[p] * DK + (c - 128)];
        X[r][c] = v;
    }
    if (tid < 8) AV[tid] = (float)ansv[base + tid];
    __syncthreads();

    const int k = tid;
    const float4* wrow = (const float4*)(W1 + k * 384);
    float rs = 0.f;
#pragma unroll
    for (int j4 = 64; j4 < 96; ++j4) { float4 w = wrow[j4]; rs += w.x + w.y + w.z + w.w; }
    float acc[8];
    const float bk = b1[k];
#pragma unroll
    for (int r = 0; r < 8; ++r) acc[r] = bk + AV[r] * rs;
    for (int j4 = 0; j4 < 64; ++j4) {
        float4 w = wrow[j4];
#pragma unroll
        for (int r = 0; r < 8; ++r) {
            float4 x = ((const float4*)X[r])[j4];
            acc[r] = fmaf(x.x, w.x, acc[r]); acc[r] = fmaf(x.y, w.y, acc[r]);
            acc[r] = fmaf(x.z, w.z, acc[r]); acc[r] = fmaf(x.w, w.w, acc[r]);
        }
    }
#pragma unroll
    for (int r = 0; r < 8; ++r) g_le[(base + r) * DK + k] = acc[r];
}

// ------------------------------------------------------------------
__global__ void pre_kernel(const int* __restrict__ eid, const int* __restrict__ itid,
                           const float* __restrict__ ex_table, const float* __restrict__ it_table,
                           const float* __restrict__ Wl, const float* __restrict__ bl,
                           const float* __restrict__ Wg, const float* __restrict__ bg,
                           const float* __restrict__ Wf, const float* __restrict__ bf,
                           const float* __restrict__ Wp, const float* __restrict__ bp)
{
    __shared__ float X[16][512];
    const int tid  = threadIdx.x;
    const int base = blockIdx.x * 16;

    for (int idx = tid; idx < 16 * 512; idx += 512) {
        int r = idx >> 9, c = idx & 511;
        int p = base + r;
        int b = p / NSTEP, t = p % NSTEP;
        float v;
        if (c < 128)      v = (t == 0) ? 0.f : g_le[(b * SEQ + t - 1) * DK + c];
        else if (c < 256) v = it_table[itid[b * SEQ + t + 1] * DK + (c - 128)];
        else if (c < 384) v = g_le[(b * SEQ + t) * DK + (c - 256)];
        else              v = ex_table[eid[b * SEQ + t + 1] * DK + (c - 384)];
        X[r][c] = v;
    }
    __syncthreads();

    const int g = tid >> 7, k = tid & 127;
    float acc[16];

    if (g <= 1) {
        const float* W = (g == 0) ? Wl : Wg;
        const float  bk = (g == 0) ? bl[k] : bg[k];
#pragma unroll
        for (int r = 0; r < 16; ++r) acc[r] = bk;
        const float4* wrow = (const float4*)(W + k * 512);
        for (int j4 = 0; j4 < 96; ++j4) {
            float4 w = wrow[j4];
#pragma unroll
            for (int r = 0; r < 16; ++r) {
                float4 x = ((const float4*)X[r])[j4];
                acc[r] = fmaf(x.x, w.x, acc[r]); acc[r] = fmaf(x.y, w.y, acc[r]);
                acc[r] = fmaf(x.z, w.z, acc[r]); acc[r] = fmaf(x.w, w.w, acc[r]);
            }
        }
        float* dst = (g == 0) ? g_Al : g_Ag;
#pragma unroll
        for (int r = 0; r < 16; ++r) dst[(base + r) * DK + k] = acc[r];
    } else if (g == 2) {
        const float bk = bf[k];
#pragma unroll
        for (int r = 0; r < 16; ++r) acc[r] = bk;
        const float4* wrow = (const float4*)(Wf + k * 384 + 256);
        for (int j4 = 0; j4 < 32; ++j4) {
            float4 w = wrow[j4];
#pragma unroll
            for (int r = 0; r < 16; ++r) {
                float4 x = ((const float4*)(X[r] + 128))[j4];
                acc[r] = fmaf(x.x, w.x, acc[r]); acc[r] = fmaf(x.y, w.y, acc[r]);
                acc[r] = fmaf(x.z, w.z, acc[r]); acc[r] = fmaf(x.w, w.w, acc[r]);
            }
        }
#pragma unroll
        for (int r = 0; r < 16; ++r) g_Af[(base + r) * DK + k] = acc[r];
    } else {
        const float bk = bp[k];
#pragma unroll
        for (int r = 0; r < 16; ++r) acc[r] = bk;
        const float4* wrow = (const float4*)(Wp + k * 256);
        for (int j4 = 0; j4 < 32; ++j4) {
            float4 w = wrow[j4];
#pragma unroll
            for (int r = 0; r < 16; ++r) {
                float4 x = ((const float4*)(X[r] + 384))[j4];
                acc[r] = fmaf(x.x, w.x, acc[r]); acc[r] = fmaf(x.y, w.y, acc[r]);
                acc[r] = fmaf(x.z, w.z, acc[r]); acc[r] = fmaf(x.w, w.w, acc[r]);
            }
        }
#pragma unroll
        for (int r = 0; r < 16; ++r) g_Ap[(base + r) * DK + k] = acc[r];
    }
}

// ------------------------------------------------------------------
// Kernel 3: hybrid dual-pipe recurrent loop.
//   warps 0-3: cols 0-63, 3-pass bf16 mma.sync (tensor pipe)
//   warps 4-7: cols 64-127, exact fp32 f32x2 FFMA (fma pipe)
//   warps 8-11: chain
static constexpr int OFF_AHI  = 0;        // 64*272
static constexpr int OFF_ALO  = 17408;
static constexpr int OFF_BHI  = 34816;    // 64*272, single buffer
static constexpr int OFF_BLO  = 52224;    // = BHI+17408
static constexpr int OFF_HS   = 69632;    // 64*132*4
static constexpr int OFF_WS   = 103424;   // Wf0 cols 64-127, [j][c']: 128*68*4
static constexpr int OFF_WL2  = 138240;
static constexpr int OFF_WG2  = 155136;
static constexpr int OFF_WF1  = 172032;
static constexpr int OFF_WP1  = 188928;
static constexpr int OFF_MAIL = 205824;
static constexpr int OFF_LGF  = 209920;
static constexpr int OFF_CFF  = 210944;
static constexpr int OFF_HT   = 211968;
static constexpr int OFF_LGT  = 212480;
static constexpr int OFF_KV   = 212736;
static constexpr int OFF_BAR  = 213248;
static constexpr int SMEM_BYTES = 213296;

#define BARH_B(buf)  (OFF_BAR + (buf) * 8)
#define BARLG_B(buf) (OFF_BAR + 16 + (buf) * 8)
#define BARCF_B(buf) (OFF_BAR + 32 + (buf) * 8)

__global__ void __cluster_dims__(CL, 1, 1) __launch_bounds__(NT, 1)
recur_kernel(const int* __restrict__ eid, const float* __restrict__ qmat,
             const float* __restrict__ Wl, const float* __restrict__ Wg,
             const float* __restrict__ Wf, const float* __restrict__ Wp,
             const float* __restrict__ h0, float* __restrict__ out)
{
    extern __shared__ float sm[];
    char*  smc  = (char*)sm;
    float* hSf  = (float*)(smc + OFF_HS);
    float* wl2  = (float*)(smc + OFF_WL2);
    float* wg2  = (float*)(smc + OFF_WG2);
    float* wf1  = (float*)(smc + OFF_WF1);
    float* wp1  = (float*)(smc + OFF_WP1);
    float* mail = (float*)(smc + OFF_MAIL);
    float* LGf  = (float*)(smc + OFF_LGF);
    float* cff  = (float*)(smc + OFF_CFF);
    float* htil = (float*)(smc + OFF_HT);
    float* lgt  = (float*)(smc + OFF_LGT);
    float* kv   = (float*)(smc + OFF_KV);

    const unsigned sbase = smem_u32(sm);
    const int tid   = threadIdx.x;
    const int wid   = tid >> 5;
    const int lane  = tid & 31;
    const int b     = blockIdx.x / CL;
    const int r     = (int)my_cluster_rank();
    const int sBase = r * SKP;

    if (tid == 0) {
        mbar_init(sbase + BARH_B(0), 192);  mbar_init(sbase + BARH_B(1), 192);
        mbar_init(sbase + BARLG_B(0), 128); mbar_init(sbase + BARLG_B(1), 128);
        mbar_init(sbase + BARCF_B(0), 128); mbar_init(sbase + BARCF_B(1), 128);
    }

    // Wf0 rows 0-63 -> bf16 hi/lo A tiles; rows 64-127 -> fp32 [j][c'] tile
    for (int idx = tid; idx < 64 * DK; idx += NT) {
        int c = idx >> 7, k = idx & 127;
        float w = Wf[c * 384 + k];
        __nv_bfloat16 hi = __float2bfloat16(w);
        float hif = __uint_as_float(((unsigned)__bfloat16_as_ushort(hi)) << 16);
        __nv_bfloat16 lo = __float2bfloat16(w - hif);
        unsigned off = (unsigned)(c * AST + k) * 2;
        *(__nv_bfloat16*)(smc + OFF_AHI + off) = hi;
        *(__nv_bfloat16*)(smc + OFF_ALO + off) = lo;
    }
    for (int idx = tid; idx < 64 * DK; idx += NT) {
        int c = 64 + (idx >> 7), k = idx & 127;
        ((float*)(smc + OFF_WS))[k * 68 + (c - 64)] = Wf[c * 384 + k];
    }
    for (int idx = tid; idx < 32 * DK; idx += NT) {
        int row = idx >> 7, k = idx & 127;
        int gk = r * 32 + row;
        wl2[row * WST + k] = Wl[gk * 512 + 384 + k];
        wg2[row * WST + k] = Wg[gk * 512 + 384 + k];
        wf1[row * WST + k] = Wf[gk * 384 + 128 + k];
        wp1[row * WST + k] = Wp[gk * 256 + 128 + k];
    }
    if (tid < SKP) kv[tid] = qmat[eid[b * SEQ] * NSKILL + sBase + tid];
    __syncthreads();

    // identities
    const int grp = lane >> 2, tid4 = lane & 3;
    const int c0  = wid * 16 + grp;                          // tensor cols
    const unsigned aoff = (unsigned)((wid * 16 + (lane & 15)) * AST + ((lane >> 4) << 3)) * 2;
    const int brow = (lane & 7) + ((lane >> 4) << 3);
    const int bcol = ((lane >> 3) & 1) << 3;
    const int w4 = wid - 4, cL = lane & 3, sL = lane >> 2;
    const int cB = 64 + w4 * 16 + cL * 4;                    // ffma cols

    float h[8][4];

    if (tid < 256) {
        if (wid < 4) {
            float pk0 = 0.f, pk1 = 0.f;
#pragma unroll
            for (int nt = 0; nt < 8; ++nt) {
                const int s0 = nt * 8 + tid4 * 2;
                const float k0 = kv[s0], k1 = kv[s0 + 1];
                h[nt][0] = h0[(sBase + s0) * DK + c0];
                h[nt][1] = h0[(sBase + s0 + 1) * DK + c0];
                h[nt][2] = h0[(sBase + s0) * DK + c0 + 8];
                h[nt][3] = h0[(sBase + s0 + 1) * DK + c0 + 8];
                st_split(smc, OFF_BHI, s0,     c0,     h[nt][0]);
                st_split(smc, OFF_BHI, s0 + 1, c0,     h[nt][1]);
                st_split(smc, OFF_BHI, s0,     c0 + 8, h[nt][2]);
                st_split(smc, OFF_BHI, s0 + 1, c0 + 8, h[nt][3]);
                hSf[s0 * HST + c0]           = h[nt][0];
                hSf[(s0 + 1) * HST + c0]     = h[nt][1];
                hSf[s0 * HST + c0 + 8]       = h[nt][2];
                hSf[(s0 + 1) * HST + c0 + 8] = h[nt][3];
                pk0 = fmaf(k0, h[nt][0], pk0); pk0 = fmaf(k1, h[nt][1], pk0);
                pk1 = fmaf(k0, h[nt][2], pk1); pk1 = fmaf(k1, h[nt][3], pk1);
            }
            pk0 += __shfl_xor_sync(0xffffffffu, pk0, 1);
            pk0 += __shfl_xor_sync(0xffffffffu, pk0, 2);
            pk1 += __shfl_xor_sync(0xffffffffu, pk1, 1);
            pk1 += __shfl_xor_sync(0xffffffffu, pk1, 2);
            if (tid4 == 0) {
                unsigned la = sbase + OFF_MAIL + (unsigned)(r * DK + c0) * 4;
#pragma unroll
                for (int rr = 0; rr < CL; ++rr) {
                    unsigned ra = mapa_rank(la, rr);
                    st_cluster_f32(ra, pk0);
                    st_cluster_f32(ra + 32, pk1);
                }
            }
        } else {
            float pk[4] = {0.f, 0.f, 0.f, 0.f};
#pragma unroll
            for (int i = 0; i < 8; ++i) {
                const int s = sL + 8 * i;
                const float kk = kv[s];
                float4 hv = *(const float4*)(h0 + (sBase + s) * DK + cB);
                h[i][0] = hv.x; h[i][1] = hv.y; h[i][2] = hv.z; h[i][3] = hv.w;
                *(float4*)(hSf + s * HST + cB) = hv;
                unsigned hi01 = bfpack(hv.x, hv.y), hi23 = bfpack(hv.z, hv.w);
                float r0 = hv.x - __uint_as_float(hi01 << 16);
                float r1 = hv.y - __uint_as_float(hi01 & 0xFFFF0000u);
                float r2 = hv.z - __uint_as_float(hi23 << 16);
                float r3 = hv.w - __uint_as_float(hi23 & 0xFFFF0000u);
                unsigned lo01 = bfpack(r0, r1), lo23 = bfpack(r2, r3);
                unsigned ba = sbase + OFF_BHI + (unsigned)(s * AST + cB) * 2;
                asm volatile("st.shared.v2.u32 [%0], {%1,%2};" :: "r"(ba), "r"(hi01), "r"(hi23));
                asm volatile("st.shared.v2.u32 [%0], {%1,%2};" :: "r"(ba + 17408), "r"(lo01), "r"(lo23));
                pk[0] = fmaf(kk, hv.x, pk[0]); pk[1] = fmaf(kk, hv.y, pk[1]);
                pk[2] = fmaf(kk, hv.z, pk[2]); pk[3] = fmaf(kk, hv.w, pk[3]);
            }
#pragma unroll
            for (int m = 4; m <= 16; m <<= 1)
#pragma unroll
                for (int q = 0; q < 4; ++q) pk[q] += __shfl_xor_sync(0xffffffffu, pk[q], m);
            if (sL == 0) {
                unsigned la = sbase + OFF_MAIL + (unsigned)(r * DK + cB) * 4;
#pragma unroll
                for (int rr = 0; rr < CL; ++rr) {
                    unsigned ra = mapa_rank(la, rr);
#pragma unroll
                    for (int q = 0; q < 4; ++q) st_cluster_f32(ra + 4 * q, pk[q]);
                }
            }
        }
    }
    __syncthreads();
    cluster_sync_all();

    if (tid < 256) {
        int phLG[2] = {0, 0}, phCF[2] = {0, 0};

        if (wid < 4) {
            // ===== tensor warps: cols 0-63 =====
            for (int t = 0; t < NSTEP; ++t) {
                const int buf = t & 1, nbuf = buf ^ 1;
                float acc[8][4];
#pragma unroll
                for (int nt = 0; nt < 8; ++nt)
#pragma unroll
                    for (int q = 0; q < 4; ++q) acc[nt][q] = 0.f;

                const unsigned bb = sbase + OFF_BHI;
#pragma unroll
                for (int kk = 0; kk < 8; ++kk) {
                    unsigned ah[4], al[4];
                    LDSM4(ah, sbase + OFF_AHI + aoff + kk * 32);
                    LDSM4(al, sbase + OFF_ALO + aoff + kk * 32);
#pragma unroll
                    for (int ntp = 0; ntp < 4; ++ntp) {
                        unsigned bh[4], bl[4];
                        unsigned bo = (unsigned)((ntp * 16 + brow) * AST + bcol + kk * 16) * 2;
                        LDSM4(bh, bb + bo);
                        LDSM4(bl, bb + 17408 + bo);
                        MMA16816(acc[2 * ntp],     ah, bh[0], bh[1]);
                        MMA16816(acc[2 * ntp],     ah, bl[0], bl[1]);
                        MMA16816(acc[2 * ntp],     al, bh[0], bh[1]);
                        MMA16816(acc[2 * ntp + 1], ah, bh[2], bh[3]);
                        MMA16816(acc[2 * ntp + 1], ah, bl[2], bl[3]);
                        MMA16816(acc[2 * ntp + 1], al, bh[2], bh[3]);
                    }
                }

                bar_sync(1, 256);   // all GEMM reads of B/hS complete
                wait_parity(sbase + BARLG_B(buf), (unsigned)phLG[buf]); phLG[buf] ^= 1;
                wait_parity(sbase + BARCF_B(buf), (unsigned)phCF[buf]); phCF[buf] ^= 1;

                const float lg0 = LGf[buf * DK + c0], lg1 = LGf[buf * DK + c0 + 8];
                const float cf0 = cff[buf * DK + c0], cf1 = cff[buf * DK + c0 + 8];
                float pk0 = 0.f, pk1 = 0.f;
#pragma unroll
                for (int nt = 0; nt < 8; ++nt) {
                    const int s0 = nt * 8 + tid4 * 2;
                    const float2 kc = *(const float2*)(kv + buf * SKP + s0);
                    const float2 kn = *(const float2*)(kv + nbuf * SKP + s0);
                    float n0 = fmaf(sigt(acc[nt][0] + cf0), h[nt][0], kc.x * lg0);
                    float n1 = fmaf(sigt(acc[nt][1] + cf0), h[nt][1], kc.y * lg0);
                    float n2 = fmaf(sigt(acc[nt][2] + cf1), h[nt][2], kc.x * lg1);
                    float n3 = fmaf(sigt(acc[nt][3] + cf1), h[nt][3], kc.y * lg1);
                    h[nt][0] = n0; h[nt][1] = n1; h[nt][2] = n2; h[nt][3] = n3;
                    st_split(smc, OFF_BHI, s0,     c0,     n0);
                    st_split(smc, OFF_BHI, s0 + 1, c0,     n1);
                    st_split(smc, OFF_BHI, s0,     c0 + 8, n2);
                    st_split(smc, OFF_BHI, s0 + 1, c0 + 8, n3);
                    hSf[s0 * HST + c0]           = n0;
                    hSf[(s0 + 1) * HST + c0]     = n1;
                    hSf[s0 * HST + c0 + 8]       = n2;
                    hSf[(s0 + 1) * HST + c0 + 8] = n3;
                    pk0 = fmaf(kn.x, n0, pk0); pk0 = fmaf(kn.y, n1, pk0);
                    pk1 = fmaf(kn.x, n2, pk1); pk1 = fmaf(kn.y, n3, pk1);
                }
                pk0 += __shfl_xor_sync(0xffffffffu, pk0, 1);
                pk0 += __shfl_xor_sync(0xffffffffu, pk0, 2);
                pk1 += __shfl_xor_sync(0xffffffffu, pk1, 1);
                pk1 += __shfl_xor_sync(0xffffffffu, pk1, 2);
                if (tid4 == 0) {
                    unsigned la = sbase + OFF_MAIL + (unsigned)((nbuf * CL + r) * DK + c0) * 4;
#pragma unroll
                    for (int rr = 0; rr < CL; ++rr) {
                        unsigned ra = mapa_rank(la, rr);
                        st_cluster_f32(ra, pk0);
                        st_cluster_f32(ra + 32, pk1);
                    }
#pragma unroll
                    for (int rr = 0; rr < CL; ++rr)
                        arrive_cluster(mapa_rank(sbase + BARH_B(nbuf), rr));
                }
                bar_sync(1, 256);   // writes done before next GEMM
            }
        } else {
            // ===== ffma warps: cols 64-127, exact fp32 =====
            const float* wrow = (const float*)(smc + OFF_WS) + w4 * 16 + cL * 4;
            for (int t = 0; t < NSTEP; ++t) {
                const int buf = t & 1, nbuf = buf ^ 1;

                unsigned long long a2[8][2];
#pragma unroll
                for (int i = 0; i < 8; ++i) { a2[i][0] = 0ull; a2[i][1] = 0ull; }

#pragma unroll 4
                for (int jj = 0; jj < DK; jj += 4) {
                    ulonglong2 w0 = *(const ulonglong2*)(wrow + (jj + 0) * 68);
                    ulonglong2 w1 = *(const ulonglong2*)(wrow + (jj + 1) * 68);
                    ulonglong2 w2 = *(const ulonglong2*)(wrow + (jj + 2) * 68);
                    ulonglong2 w3 = *(const ulonglong2*)(wrow + (jj + 3) * 68);
#pragma unroll
                    for (int i = 0; i < 8; ++i) {
                        float4 hv = *(const float4*)(hSf + (sL + 8 * i) * HST + jj);
                        unsigned long long hx;
                        hx = f2dup(hv.x);
                        a2[i][0] = fma2(hx, w0.x, a2[i][0]); a2[i][1] = fma2(hx, w0.y, a2[i][1]);
                        hx = f2dup(hv.y);
                        a2[i][0] = fma2(hx, w1.x, a2[i][0]); a2[i][1] = fma2(hx, w1.y, a2[i][1]);
                        hx = f2dup(hv.z);
                        a2[i][0] = fma2(hx, w2.x, a2[i][0]); a2[i][1] = fma2(hx, w2.y, a2[i][1]);
                        hx = f2dup(hv.w);
                        a2[i][0] = fma2(hx, w3.x, a2[i][0]); a2[i][1] = fma2(hx, w3.y, a2[i][1]);
                    }
                }

                bar_sync(1, 256);
                wait_parity(sbase + BARLG_B(buf), (unsigned)phLG[buf]); phLG[buf] ^= 1;
                wait_parity(sbase + BARCF_B(buf), (unsigned)phCF[buf]); phCF[buf] ^= 1;

                float4 lg4 = *(const float4*)(LGf + buf * DK + cB);
                float4 cf4 = *(const float4*)(cff + buf * DK + cB);
                float pk[4] = {0.f, 0.f, 0.f, 0.f};
#pragma unroll
                for (int i = 0; i < 8; ++i) {
                    const int s = sL + 8 * i;
                    const float kc = kv[buf * SKP + s];
                    const float kn = kv[nbuf * SKP + s];
                    float2 fa0 = f2unpack(a2[i][0]);
                    float2 fa1 = f2unpack(a2[i][1]);
                    float n0 = fmaf(sigt(fa0.x + cf4.x), h[i][0], kc * lg4.x);
                    float n1 = fmaf(sigt(fa0.y + cf4.y), h[i][1], kc * lg4.y);
                    float n2 = fmaf(sigt(fa1.x + cf4.z), h[i][2], kc * lg4.z);
                    float n3 = fmaf(sigt(fa1.y + cf4.w), h[i][3], kc * lg4.w);
                    h[i][0] = n0; h[i][1] = n1; h[i][2] = n2; h[i][3] = n3;
                    *(float4*)(hSf + s * HST + cB) = make_float4(n0, n1, n2, n3);
                    unsigned hi01 = bfpack(n0, n1), hi23 = bfpack(n2, n3);
                    float r0 = n0 - __uint_as_float(hi01 << 16);
                    float r1 = n1 - __uint_as_float(hi01 & 0xFFFF0000u);
                    float r2 = n2 - __uint_as_float(hi23 << 16);
                    float r3 = n3 - __uint_as_float(hi23 & 0xFFFF0000u);
                    unsigned lo01 = bfpack(r0, r1), lo23 = bfpack(r2, r3);
                    unsigned ba = sbase + OFF_BHI + (unsigned)(s * AST + cB) * 2;
                    asm volatile("st.shared.v2.u32 [%0], {%1,%2};" :: "r"(ba), "r"(hi01), "r"(hi23));
                    asm volatile("st.shared.v2.u32 [%0], {%1,%2};" :: "r"(ba + 17408), "r"(lo01), "r"(lo23));
                    pk[0] = fmaf(kn, n0, pk[0]); pk[1] = fmaf(kn, n1, pk[1]);
                    pk[2] = fmaf(kn, n2, pk[2]); pk[3] = fmaf(kn, n3, pk[3]);
                }
#pragma unroll
                for (int m = 4; m <= 16; m <<= 1)
#pragma unroll
                    for (int q = 0; q < 4; ++q) pk[q] += __shfl_xor_sync(0xffffffffu, pk[q], m);
                if (sL == 0) {
                    unsigned la = sbase + OFF_MAIL + (unsigned)((nbuf * CL + r) * DK + cB) * 4;
#pragma unroll
                    for (int rr = 0; rr < CL; ++rr) {
                        unsigned ra = mapa_rank(la, rr);
#pragma unroll
                        for (int q = 0; q < 4; ++q) st_cluster_f32(ra + 4 * q, pk[q]);
                    }
#pragma unroll
                    for (int rr = 0; rr < CL; ++rr)
                        arrive_cluster(mapa_rank(sbase + BARH_B(nbuf), rr));
                }
                bar_sync(1, 256);
            }
        }
    } else {
        // ===== chain warps (identical to R8) =====
        const int tc   = tid - 256;
        const int rowB = tc >> 1, qB = tc & 1;
        const int rowD = tc >> 2, qD = tc & 3;
        const float* wB = ((rowB < 32) ? (wl2 + rowB * WST) : (wg2 + (rowB - 32) * WST)) + qB * 64;
        int phH[2] = {0, 0}, phLG[2] = {0, 0};

        for (int t = 0; t < NSTEP; ++t) {
            const int buf = t & 1, nbuf = buf ^ 1;
            const int ptA = (b * NSTEP + t) * DK;

            if (t > 0) { wait_parity(sbase + BARH_B(buf), (unsigned)phH[buf]); phH[buf] ^= 1; }
            {
                const float* m = mail + buf * CL * DK + tc;
                htil[tc] = m[0] + m[DK] + m[2 * DK] + m[3 * DK];
            }
            bar_sync(2, 128);

            if (qD == 0) {
                const int e = eid[b * SEQ + t + 1] * NSKILL + sBase;
                kv[nbuf * SKP + rowD]      = qmat[e + rowD];
                kv[nbuf * SKP + 32 + rowD] = qmat[e + 32 + rowD];
            }

            {
                float a = 0.f;
                const float* hp = htil + qB * 64;
#pragma unroll
                for (int j4 = 0; j4 < 16; ++j4) {
                    float4 w = ((const float4*)wB)[j4];
                    float4 hh = ((const float4*)hp)[j4];
                    a = fmaf(hh.x, w.x, a); a = fmaf(hh.y, w.y, a);
                    a = fmaf(hh.z, w.z, a); a = fmaf(hh.w, w.w, a);
                }
                a += __shfl_xor_sync(0xffffffffu, a, 1);
                if (qB == 0) lgt[rowB] = a;
            }
            bar_sync(2, 128);

            if (tc < 32) {
                const int k = r * 32 + tc;
                float lgp = g_Al[ptA + k] + lgt[tc];
                float gtp = g_Ag[ptA + k] + lgt[32 + tc];
                float val = sigm(gtp) * sigm(2.f * lgp);
                unsigned la = sbase + OFF_LGF + (unsigned)(buf * DK + k) * 4;
#pragma unroll
                for (int rr = 0; rr < CL; ++rr) st_cluster_f32(mapa_rank(la, rr), val);
#pragma unroll
                for (int rr = 0; rr < CL; ++rr)
                    arrive_cluster(mapa_rank(sbase + BARLG_B(buf), rr));
            }

            if (t > 0) {
                float a = 0.f;
                const float* wf = wp1 + rowD * WST + qD * 32;
                const float* hp = htil + qD * 32;
#pragma unroll
                for (int j4 = 0; j4 < 8; ++j4) {
                    float4 w = ((const float4*)wf)[j4];
                    float4 hh = ((const float4*)hp)[j4];
                    a = fmaf(hh.x, w.x, a); a = fmaf(hh.y, w.y, a);
                    a = fmaf(hh.z, w.z, a); a = fmaf(hh.w, w.w, a);
                }
                a += __shfl_xor_sync(0xffffffffu, a, 1);
                a += __shfl_xor_sync(0xffffffffu, a, 2);
                if (qD == 0) {
                    const int k = r * 32 + rowD;
                    out[(b * NSTEP + (t - 1)) * DK + k] =
                        sigm(a + g_Ap[(b * NSTEP + (t - 1)) * DK + k]);
                }
            }

            wait_parity(sbase + BARLG_B(buf), (unsigned)phLG[buf]); phLG[buf] ^= 1;
            {
                float a = 0.f;
                const float* wf = wf1 + rowD * WST + qD * 32;
                const float* lp = LGf + buf * DK + qD * 32;
#pragma unroll
                for (int j4 = 0; j4 < 8; ++j4) {
                    float4 w = ((const float4*)wf)[j4];
                    float4 hh = ((const float4*)lp)[j4];
                    a = fmaf(hh.x, w.x, a); a = fmaf(hh.y, w.y, a);
                    a = fmaf(hh.z, w.z, a); a = fmaf(hh.w, w.w, a);
                }
                a += __shfl_xor_sync(0xffffffffu, a, 1);
                a += __shfl_xor_sync(0xffffffffu, a, 2);
                if (qD == 0) {
                    const int k = r * 32 + rowD;
                    float val = a + g_Af[ptA + k];
                    unsigned la = sbase + OFF_CFF + (unsigned)(buf * DK + k) * 4;
#pragma unroll
                    for (int rr = 0; rr < CL; ++rr) st_cluster_f32(mapa_rank(la, rr), val);
#pragma unroll
                    for (int rr = 0; rr < CL; ++rr)
                        arrive_cluster(mapa_rank(sbase + BARCF_B(buf), rr));
                }
            }
        }

        wait_parity(sbase + BARH_B(NSTEP & 1), (unsigned)phH[NSTEP & 1]);
        {
            const float* m = mail + (NSTEP & 1) * CL * DK + tc;
            htil[tc] = m[0] + m[DK] + m[2 * DK] + m[3 * DK];
        }
        bar_sync(2, 128);
        {
            float a = 0.f;
            const float* wf = wp1 + rowD * WST + qD * 32;
            const float* hp = htil + qD * 32;
#pragma unroll
            for (int j4 = 0; j4 < 8; ++j4) {
                float4 w = ((const float4*)wf)[j4];
                float4 hh = ((const float4*)hp)[j4];
                a = fmaf(hh.x, w.x, a); a = fmaf(hh.y, w.y, a);
                a = fmaf(hh.z, w.z, a); a = fmaf(hh.w, w.w, a);
            }
            a += __shfl_xor_sync(0xffffffffu, a, 1);
            a += __shfl_xor_sync(0xffffffffu, a, 2);
            if (qD == 0) {
                const int k = r * 32 + rowD;
                out[(b * NSTEP + (NSTEP - 1)) * DK + k] =
                    sigm(a + g_Ap[(b * NSTEP + (NSTEP - 1)) * DK + k]);
            }
        }
    }

    cluster_sync_all();
}

// ------------------------------------------------------------------
extern "C" void kernel_launch(void* const* d_in, const int* in_sizes, int n_in,
                              void* d_out, int out_size)
{
    const int*   eid      = (const int*)d_in[0];
    const int*   atid     = (const int*)d_in[1];
    const int*   itid     = (const int*)d_in[2];
    const int*   ansv     = (const int*)d_in[3];
    const float* qmat     = (const float*)d_in[4];
    const float* ex_table = (const float*)d_in[5];
    const float* at_table = (const float*)d_in[6];
    const float* it_table = (const float*)d_in[7];
    const float* W1       = (const float*)d_in[8];
    const float* b1       = (const float*)d_in[9];
    const float* Wl       = (const float*)d_in[10];
    const float* bl       = (const float*)d_in[11];
    const float* Wg       = (const float*)d_in[12];
    const float* bg       = (const float*)d_in[13];
    const float* Wf       = (const float*)d_in[14];
    const float* bf       = (const float*)d_in[15];
    const float* Wp       = (const float*)d_in[16];
    const float* bp       = (const float*)d_in[17];
    const float* h0       = (const float*)d_in[18];
    float* out = (float*)d_out;

    cudaFuncSetAttribute(recur_kernel, cudaFuncAttributeMaxDynamicSharedMemorySize, SMEM_BYTES);

    le_kernel<<<(BATCH * SEQ) / 8, 128>>>(eid, atid, ansv, ex_table, at_table, W1, b1);
    pre_kernel<<<(BATCH * NSTEP) / 16, 512>>>(eid, itid, ex_table, it_table,
                                              Wl, bl, Wg, bg, Wf, bf, Wp, bp);
    recur_kernel<<<BATCH * CL, NT, SMEM_BYTES>>>(eid, qmat, Wl, Wg, Wf, Wp, h0, out);
}